// round 1
// baseline (speedup 1.0000x reference)
#include <cuda_runtime.h>
#include <cuda_bf16.h>

// Problem constants
#define MAP_W   64
#define MAP_H   64
#define T_SIZE  64
#define NUM_CP  8
#define BATCH   128

// Binomial coefficients C(m, k) for m = 0..7 (only m=2..7 used at runtime)
__device__ const float BINOM[8][8] = {
    {1, 0, 0,  0,  0,  0,  0, 0},
    {1, 1, 0,  0,  0,  0,  0, 0},
    {1, 2, 1,  0,  0,  0,  0, 0},
    {1, 3, 3,  1,  0,  0,  0, 0},
    {1, 4, 6,  4,  1,  0,  0, 0},
    {1, 5, 10, 10, 5,  1,  0, 0},
    {1, 6, 15, 20, 15, 6,  1, 0},
    {1, 7, 21, 35, 35, 21, 7, 1},
};

// Block: 256 threads = 64 t-lanes x 4 y-groups. Each block owns (b, 4 x-cols).
// Grid: BATCH * (MAP_W/4) = 2048 blocks.
__global__ __launch_bounds__(256, 4)
void probmap_kernel(const float* __restrict__ cp_means,
                    const int*   __restrict__ num_cps,
                    const float* __restrict__ cp_cov,
                    float*       __restrict__ out)
{
    const int b  = blockIdx.x >> 4;          // batch index
    const int x0 = (blockIdx.x & 15) << 2;   // first of 4 x columns
    const int t   = threadIdx.x & 63;        // lane -> t (contiguous stores)
    const int grp = threadIdx.x >> 6;        // 0..3 y-group

    const int m = num_cps[b] - 1;            // degree, 2..7 (uniform per block)

    // ---- Bernstein weights for this t ----
    const float tt = (float)t * (1.0f / 63.0f);
    const float u  = 1.0f - tt;

    float up[NUM_CP];                        // u^j
    up[0] = 1.0f;
    #pragma unroll
    for (int j = 1; j < NUM_CP; j++) up[j] = up[j - 1] * u;

    float w[NUM_CP];
    {
        float tk = 1.0f;                     // tt^k
        #pragma unroll
        for (int k = 0; k < NUM_CP; k++) {
            float wk = 0.0f;
            if (k <= m) wk = BINOM[m][k] * tk * up[m - k];
            w[k] = wk;
            tk *= tt;
        }
    }

    // ---- Weighted mean and covariance (broadcast loads: same b for all lanes) ----
    float mx = 0.f, my = 0.f, ca = 0.f, cb = 0.f, cd = 0.f;
    #pragma unroll
    for (int k = 0; k < NUM_CP; k++) {
        const float wk = w[k];
        const float w2 = wk * wk;
        const float* mp = cp_means + ((size_t)k * BATCH + b) * 2;
        const float* cp = cp_cov   + (((size_t)k * BATCH + b) * 2) * 2;
        mx += wk * __ldg(mp + 0);
        my += wk * __ldg(mp + 1);
        ca += w2 * __ldg(cp + 0);   // cov[0][0]
        cb += w2 * __ldg(cp + 1);   // cov[0][1] (== cov[1][0], symmetric)
        cd += w2 * __ldg(cp + 3);   // cov[1][1]
    }

    // ---- 2x2 inverse folded with -0.5*log2(e) so inner loop uses exp2 ----
    const float det  = ca * cd - cb * cb;
    const float rdet = 1.0f / det;
    const float NL2E = -0.72134752044448170f;          // -0.5 * log2(e)
    const float Af = NL2E * cd * rdet;                 // coeff of dx^2
    const float Bf = -2.0f * NL2E * cb * rdet;         // coeff of dx*dy (= +log2e*cb*rdet)
    const float Cf = NL2E * ca * rdet;                 // coeff of dy^2
    const float scale = rsqrtf(39.478417604357434f * det); // 1/sqrt((2pi)^2 det)

    // ---- Main evaluation: 4 x-columns, y strided by 4 groups, lane = t ----
    #pragma unroll
    for (int xi = 0; xi < 4; xi++) {
        const int x = x0 + xi;
        const float dx   = (float)x - mx;
        const float Adx2 = Af * dx * dx;
        const float Bdx  = Bf * dx;
        float* orow = out + ((((size_t)b * MAP_W + x) * MAP_H) * T_SIZE) + t;

        float dy = (float)grp - my;
        #pragma unroll
        for (int yi = 0; yi < MAP_H / 4; yi++) {
            const float e2 = fmaf(Cf * dy, dy, fmaf(Bdx, dy, Adx2));
            const float v  = exp2f(e2) * scale;
            __stcs(orow + ((size_t)(grp + 4 * yi)) * T_SIZE, v);
            dy += 4.0f;
        }
    }
}

extern "C" void kernel_launch(void* const* d_in, const int* in_sizes, int n_in,
                              void* d_out, int out_size)
{
    const float* cp_means = (const float*)d_in[0];   // (8, 128, 2)
    const int*   num_cps  = (const int*)  d_in[1];   // (128,)
    const float* cp_cov   = (const float*)d_in[2];   // (8, 128, 2, 2)
    float* out = (float*)d_out;                      // (128, 64, 64, 64)

    dim3 grid(BATCH * (MAP_W / 4));
    dim3 block(256);
    probmap_kernel<<<grid, block>>>(cp_means, num_cps, cp_cov, out);
}